// round 1
// baseline (speedup 1.0000x reference)
#include <cuda_runtime.h>
#include <cstdint>

#define IN_SIZE  65536
#define OUT_SIZE 65536
#define NNZ      1048576
#define BATCH    32

// Scratch in [node][batch] layout: one edge touches one contiguous 128B line.
__device__ __align__(256) float g_xt[IN_SIZE  * BATCH];  // x transposed  [src][b]
__device__ __align__(256) float g_ot[OUT_SIZE * BATCH];  // out transposed [dst][b]

// ---------------------------------------------------------------------------
// Kernel 1: tiled transpose x[32, IN_SIZE] -> g_xt[IN_SIZE, 32],
// and zero g_ot (same index range, fused to save a launch + pass).
// Block (32,32), grid IN_SIZE/32 = 2048.
// ---------------------------------------------------------------------------
__global__ void transpose_in_kernel(const float* __restrict__ x) {
    __shared__ float tile[32][33];
    const int src0 = blockIdx.x * 32;
    const int tx = threadIdx.x, ty = threadIdx.y;

    // Coalesced read: row b=ty, columns src0+tx
    tile[ty][tx] = x[ty * IN_SIZE + src0 + tx];
    // Zero the matching chunk of out_t (coalesced write)
    g_ot[(src0 + ty) * 32 + tx] = 0.0f;
    __syncthreads();
    // Coalesced write: x_t[src0+ty][tx]
    g_xt[(src0 + ty) * 32 + tx] = tile[tx][ty];
}

// ---------------------------------------------------------------------------
// Kernel 2: edge scatter. 8 threads per edge, one float4 per thread.
// Gather 128B from g_xt (L2-resident), scale by w, vector-atomic into g_ot.
// ---------------------------------------------------------------------------
__global__ void edge_kernel(const float* __restrict__ w,
                            const int*   __restrict__ dst,
                            const int*   __restrict__ src) {
    const int idx = blockIdx.x * blockDim.x + threadIdx.x;
    const int e = idx >> 3;        // edge id
    const int j = idx & 7;         // float4 slot within the 32-float row
    if (e >= NNZ) return;

    const int   s  = src[e];
    const int   d  = dst[e];
    const float we = w[e];

    float4 v = *(reinterpret_cast<const float4*>(g_xt + (size_t)s * 32) + j);
    v.x *= we; v.y *= we; v.z *= we; v.w *= we;

    float* op = g_ot + (size_t)d * 32 + j * 4;
    asm volatile("red.global.add.v4.f32 [%0], {%1, %2, %3, %4};"
                 :: "l"(op), "f"(v.x), "f"(v.y), "f"(v.z), "f"(v.w)
                 : "memory");
}

// ---------------------------------------------------------------------------
// Kernel 3: tiled transpose g_ot[OUT_SIZE, 32] -> out[32, OUT_SIZE].
// Block (32,32), grid OUT_SIZE/32 = 2048.
// ---------------------------------------------------------------------------
__global__ void transpose_out_kernel(float* __restrict__ out) {
    __shared__ float tile[32][33];
    const int d0 = blockIdx.x * 32;
    const int tx = threadIdx.x, ty = threadIdx.y;

    // Coalesced read of out_t rows
    tile[ty][tx] = g_ot[(d0 + ty) * 32 + tx];
    __syncthreads();
    // out[b=ty][d0+tx] = out_t[d0+tx][ty]  (coalesced in tx)
    out[ty * OUT_SIZE + d0 + tx] = tile[tx][ty];
}

// ---------------------------------------------------------------------------
// Launch. Inputs per metadata order: x, weights, dst_idx, src_idx.
// ---------------------------------------------------------------------------
extern "C" void kernel_launch(void* const* d_in, const int* in_sizes, int n_in,
                              void* d_out, int out_size) {
    const float* x       = (const float*)d_in[0];
    const float* weights = (const float*)d_in[1];
    const int*   dst_idx = (const int*)d_in[2];
    const int*   src_idx = (const int*)d_in[3];
    float*       out     = (float*)d_out;

    dim3 tblk(32, 32);
    transpose_in_kernel<<<IN_SIZE / 32, tblk>>>(x);

    const int threads = NNZ * 8;          // 8 threads per edge
    const int bs = 256;
    edge_kernel<<<(threads + bs - 1) / bs, bs>>>(weights, dst_idx, src_idx);

    transpose_out_kernel<<<OUT_SIZE / 32, tblk>>>(out);
}

// round 2
// speedup vs baseline: 1.1176x; 1.1176x over previous
#include <cuda_runtime.h>
#include <cstdint>

#define IN_SIZE  65536
#define OUT_SIZE 65536
#define NNZ      1048576
#define BATCH    32

// Scratch in [node][batch] layout: one edge touches one contiguous 128B line.
__device__ __align__(256) float g_xt[IN_SIZE  * BATCH];  // x transposed  [src][b]
__device__ __align__(256) float g_ot[OUT_SIZE * BATCH];  // out transposed [dst][b]

// ---------------------------------------------------------------------------
// Kernel 1: tiled transpose x[32, IN_SIZE] -> g_xt[IN_SIZE, 32], vectorized.
// Also zeroes g_ot (fused). Block = 256 threads, tile = 32 batch x 64 cols.
// Grid = IN_SIZE/64 = 1024.
// Each thread: 2 x float4 load, 2 x float4 store to g_xt, 2 x float4 zero.
// ---------------------------------------------------------------------------
__global__ __launch_bounds__(256) void transpose_in_kernel(const float* __restrict__ x) {
    __shared__ float tile[32][65];   // [batch][col-in-tile], +1 pad
    const int src0 = blockIdx.x * 64;
    const int t = threadIdx.x;

    // Load: 32 rows x 16 float4/row = 512 float4, 2 per thread. Coalesced.
    #pragma unroll
    for (int k = 0; k < 2; k++) {
        const int q   = t + k * 256;
        const int row = q >> 4;        // batch row 0..31
        const int c4  = q & 15;        // float4 slot 0..15
        float4 v = *reinterpret_cast<const float4*>(
            x + (size_t)row * IN_SIZE + src0 + c4 * 4);
        tile[row][c4 * 4 + 0] = v.x;
        tile[row][c4 * 4 + 1] = v.y;
        tile[row][c4 * 4 + 2] = v.z;
        tile[row][c4 * 4 + 3] = v.w;
    }
    __syncthreads();

    // Store: 64 x_t rows x 8 float4/row = 512 float4, 2 per thread. Coalesced.
    const float4 z = make_float4(0.f, 0.f, 0.f, 0.f);
    #pragma unroll
    for (int k = 0; k < 2; k++) {
        const int q = t + k * 256;
        const int r = q >> 3;          // x_t row in tile 0..63
        const int j = q & 7;           // float4 slot 0..7
        float4 v = make_float4(tile[4 * j + 0][r], tile[4 * j + 1][r],
                               tile[4 * j + 2][r], tile[4 * j + 3][r]);
        *reinterpret_cast<float4*>(g_xt + (size_t)(src0 + r) * 32 + 4 * j) = v;
        *reinterpret_cast<float4*>(g_ot + (size_t)(src0 + r) * 32 + 4 * j) = z;
    }
}

// ---------------------------------------------------------------------------
// Kernel 2: edge scatter. 8 threads per edge, one float4 per thread.
// Gather 128B from g_xt (L2-resident), scale by w, vector-atomic into g_ot.
// ---------------------------------------------------------------------------
__global__ void edge_kernel(const float* __restrict__ w,
                            const int*   __restrict__ dst,
                            const int*   __restrict__ src) {
    const int idx = blockIdx.x * blockDim.x + threadIdx.x;
    const int e = idx >> 3;        // edge id
    const int j = idx & 7;         // float4 slot within the 32-float row
    if (e >= NNZ) return;

    const int   s  = src[e];
    const int   d  = dst[e];
    const float we = w[e];

    float4 v = *(reinterpret_cast<const float4*>(g_xt + (size_t)s * 32) + j);
    v.x *= we; v.y *= we; v.z *= we; v.w *= we;

    float* op = g_ot + (size_t)d * 32 + j * 4;
    asm volatile("red.global.add.v4.f32 [%0], {%1, %2, %3, %4};"
                 :: "l"(op), "f"(v.x), "f"(v.y), "f"(v.z), "f"(v.w)
                 : "memory");
}

// ---------------------------------------------------------------------------
// Kernel 3: tiled transpose g_ot[OUT_SIZE, 32] -> out[32, OUT_SIZE],
// vectorized. Block = 256, tile = 64 dst x 32 batch. Grid = OUT_SIZE/64.
// ---------------------------------------------------------------------------
__global__ __launch_bounds__(256) void transpose_out_kernel(float* __restrict__ out) {
    __shared__ float tile[32][65];   // [batch][dst-in-tile], +1 pad
    const int d0 = blockIdx.x * 64;
    const int t = threadIdx.x;

    // Load: 64 g_ot rows x 8 float4/row = 512 float4, 2 per thread. Coalesced.
    #pragma unroll
    for (int k = 0; k < 2; k++) {
        const int q = t + k * 256;
        const int r = q >> 3;          // dst row in tile 0..63
        const int j = q & 7;           // float4 slot 0..7
        float4 v = *reinterpret_cast<const float4*>(
            g_ot + (size_t)(d0 + r) * 32 + 4 * j);
        tile[4 * j + 0][r] = v.x;
        tile[4 * j + 1][r] = v.y;
        tile[4 * j + 2][r] = v.z;
        tile[4 * j + 3][r] = v.w;
    }
    __syncthreads();

    // Store: 32 out rows x 16 float4/row = 512 float4, 2 per thread. Coalesced.
    #pragma unroll
    for (int k = 0; k < 2; k++) {
        const int q  = t + k * 256;
        const int b  = q >> 4;         // batch row 0..31
        const int c4 = q & 15;         // float4 slot 0..15
        float4 v = make_float4(tile[b][4 * c4 + 0], tile[b][4 * c4 + 1],
                               tile[b][4 * c4 + 2], tile[b][4 * c4 + 3]);
        *reinterpret_cast<float4*>(out + (size_t)b * OUT_SIZE + d0 + 4 * c4) = v;
    }
}

// ---------------------------------------------------------------------------
// Launch. Inputs per metadata order: x, weights, dst_idx, src_idx.
// ---------------------------------------------------------------------------
extern "C" void kernel_launch(void* const* d_in, const int* in_sizes, int n_in,
                              void* d_out, int out_size) {
    const float* x       = (const float*)d_in[0];
    const float* weights = (const float*)d_in[1];
    const int*   dst_idx = (const int*)d_in[2];
    const int*   src_idx = (const int*)d_in[3];
    float*       out     = (float*)d_out;

    transpose_in_kernel<<<IN_SIZE / 64, 256>>>(x);

    const int threads = NNZ * 8;          // 8 threads per edge
    const int bs = 256;
    edge_kernel<<<(threads + bs - 1) / bs, bs>>>(weights, dst_idx, src_idx);

    transpose_out_kernel<<<OUT_SIZE / 64, 256>>>(out);
}

// round 3
// speedup vs baseline: 1.1546x; 1.0331x over previous
#include <cuda_runtime.h>
#include <cstdint>

#define IN_SIZE  65536
#define OUT_SIZE 65536
#define NNZ      1048576
#define BATCH    32

// Scratch in [node][batch] layout: one edge touches one contiguous 128B line.
__device__ __align__(256) float g_xt[IN_SIZE  * BATCH];  // x transposed  [src][b]
__device__ __align__(256) float g_ot[OUT_SIZE * BATCH];  // out transposed [dst][b]

// ---------------------------------------------------------------------------
// Kernel 1: tiled transpose x[32, IN_SIZE] -> g_xt[IN_SIZE, 32], vectorized,
// 2 tiles (128 columns) per block, all global loads issued up front (MLP=4).
// Also zeroes g_ot (fused). Grid = IN_SIZE/128 = 512, block = 256.
// ---------------------------------------------------------------------------
__global__ __launch_bounds__(256) void transpose_in_kernel(const float* __restrict__ x) {
    __shared__ float tile[2][32][65];   // [tile][batch][col-in-tile], +1 pad
    const int src0 = blockIdx.x * 128;
    const int t = threadIdx.x;

    // Issue all 4 independent loads first.
    float4 v[2][2];
    #pragma unroll
    for (int u = 0; u < 2; u++)
        #pragma unroll
        for (int k = 0; k < 2; k++) {
            const int q   = t + k * 256;
            const int row = q >> 4;        // batch row 0..31
            const int c4  = q & 15;        // float4 slot 0..15
            v[u][k] = *reinterpret_cast<const float4*>(
                x + (size_t)row * IN_SIZE + src0 + u * 64 + c4 * 4);
        }
    #pragma unroll
    for (int u = 0; u < 2; u++)
        #pragma unroll
        for (int k = 0; k < 2; k++) {
            const int q   = t + k * 256;
            const int row = q >> 4;
            const int c4  = q & 15;
            tile[u][row][c4 * 4 + 0] = v[u][k].x;
            tile[u][row][c4 * 4 + 1] = v[u][k].y;
            tile[u][row][c4 * 4 + 2] = v[u][k].z;
            tile[u][row][c4 * 4 + 3] = v[u][k].w;
        }
    __syncthreads();

    const float4 z = make_float4(0.f, 0.f, 0.f, 0.f);
    #pragma unroll
    for (int u = 0; u < 2; u++)
        #pragma unroll
        for (int k = 0; k < 2; k++) {
            const int q = t + k * 256;
            const int r = q >> 3;          // x_t row within 64-row tile
            const int j = q & 7;           // float4 slot 0..7
            float4 w = make_float4(tile[u][4 * j + 0][r], tile[u][4 * j + 1][r],
                                   tile[u][4 * j + 2][r], tile[u][4 * j + 3][r]);
            const size_t base = (size_t)(src0 + u * 64 + r) * 32 + 4 * j;
            *reinterpret_cast<float4*>(g_xt + base) = w;
            *reinterpret_cast<float4*>(g_ot + base) = z;
        }
}

// ---------------------------------------------------------------------------
// Kernel 2: edge scatter. 8 threads per float4-slot, 2 edges per thread
// (e and e + NNZ/2 — two independent gather+red chains in flight).
// Grid = NNZ*4/256 = 16384, exact.
// ---------------------------------------------------------------------------
__global__ __launch_bounds__(256) void edge_kernel(const float* __restrict__ w,
                                                   const int*   __restrict__ dst,
                                                   const int*   __restrict__ src) {
    const int idx = blockIdx.x * blockDim.x + threadIdx.x;
    const int e0 = idx >> 3;               // 0 .. NNZ/2-1
    const int j  = idx & 7;
    const int e1 = e0 + NNZ / 2;

    const int   s0 = src[e0], d0 = dst[e0];
    const int   s1 = src[e1], d1 = dst[e1];
    const float w0 = w[e0],   w1 = w[e1];

    float4 a = *(reinterpret_cast<const float4*>(g_xt + (size_t)s0 * 32) + j);
    float4 b = *(reinterpret_cast<const float4*>(g_xt + (size_t)s1 * 32) + j);

    a.x *= w0; a.y *= w0; a.z *= w0; a.w *= w0;
    b.x *= w1; b.y *= w1; b.z *= w1; b.w *= w1;

    float* p0 = g_ot + (size_t)d0 * 32 + j * 4;
    float* p1 = g_ot + (size_t)d1 * 32 + j * 4;
    asm volatile("red.global.add.v4.f32 [%0], {%1, %2, %3, %4};"
                 :: "l"(p0), "f"(a.x), "f"(a.y), "f"(a.z), "f"(a.w) : "memory");
    asm volatile("red.global.add.v4.f32 [%0], {%1, %2, %3, %4};"
                 :: "l"(p1), "f"(b.x), "f"(b.y), "f"(b.z), "f"(b.w) : "memory");
}

// ---------------------------------------------------------------------------
// Kernel 3: tiled transpose g_ot[OUT_SIZE, 32] -> out[32, OUT_SIZE],
// 2 tiles (128 dst rows) per block, loads issued up front (MLP=4).
// Grid = OUT_SIZE/128 = 512, block = 256.
// ---------------------------------------------------------------------------
__global__ __launch_bounds__(256) void transpose_out_kernel(float* __restrict__ out) {
    __shared__ float tile[2][32][65];   // [tile][batch][dst-in-tile], +1 pad
    const int d0 = blockIdx.x * 128;
    const int t = threadIdx.x;

    float4 v[2][2];
    #pragma unroll
    for (int u = 0; u < 2; u++)
        #pragma unroll
        for (int k = 0; k < 2; k++) {
            const int q = t + k * 256;
            const int r = q >> 3;          // dst row within 64-row tile
            const int j = q & 7;           // float4 slot 0..7
            v[u][k] = *reinterpret_cast<const float4*>(
                g_ot + (size_t)(d0 + u * 64 + r) * 32 + 4 * j);
        }
    #pragma unroll
    for (int u = 0; u < 2; u++)
        #pragma unroll
        for (int k = 0; k < 2; k++) {
            const int q = t + k * 256;
            const int r = q >> 3;
            const int j = q & 7;
            tile[u][4 * j + 0][r] = v[u][k].x;
            tile[u][4 * j + 1][r] = v[u][k].y;
            tile[u][4 * j + 2][r] = v[u][k].z;
            tile[u][4 * j + 3][r] = v[u][k].w;
        }
    __syncthreads();

    #pragma unroll
    for (int u = 0; u < 2; u++)
        #pragma unroll
        for (int k = 0; k < 2; k++) {
            const int q  = t + k * 256;
            const int b  = q >> 4;         // batch row 0..31
            const int c4 = q & 15;         // float4 slot 0..15
            float4 w = make_float4(tile[u][b][4 * c4 + 0], tile[u][b][4 * c4 + 1],
                                   tile[u][b][4 * c4 + 2], tile[u][b][4 * c4 + 3]);
            *reinterpret_cast<float4*>(
                out + (size_t)b * OUT_SIZE + d0 + u * 64 + 4 * c4) = w;
        }
}

// ---------------------------------------------------------------------------
// Launch. Inputs per metadata order: x, weights, dst_idx, src_idx.
// ---------------------------------------------------------------------------
extern "C" void kernel_launch(void* const* d_in, const int* in_sizes, int n_in,
                              void* d_out, int out_size) {
    const float* x       = (const float*)d_in[0];
    const float* weights = (const float*)d_in[1];
    const int*   dst_idx = (const int*)d_in[2];
    const int*   src_idx = (const int*)d_in[3];
    float*       out     = (float*)d_out;

    transpose_in_kernel<<<IN_SIZE / 128, 256>>>(x);
    edge_kernel<<<NNZ * 4 / 256, 256>>>(weights, dst_idx, src_idx);
    transpose_out_kernel<<<OUT_SIZE / 128, 256>>>(out);
}